// round 4
// baseline (speedup 1.0000x reference)
#include <cuda_runtime.h>
#include <stdint.h>
#include <math.h>
#include <string.h>

// ---------------------------------------------------------------------------
// Constants: L_MAX=3, N_MAX_L=[8,6,4,2], C=32, K_L=[256,192,128,64]
// feature layout per atom (1920 floats): [l0:1x256][l1:3x192][l2:5x128][l3:7x64]
// element (l,m,k) at FOFF[l] + m*KL[l] + k
// ---------------------------------------------------------------------------
#define NT        34
#define NCG       3436
#define NW        738
#define NATOM_MAX 5000
#define NPAIR_MAX 100000
#define FSTRIDE   1920

#define LIST_L1 {0,0,0,0,1,1,1,1,1,1,1,1,1,2,2,2,2,2,2,2,2,2,2,2,3,3,3,3,3,3,3,3,3,3}
#define LIST_L2 {0,1,2,3,0,1,1,1,2,2,2,3,3,0,1,1,1,2,2,2,2,3,3,3,0,1,1,2,2,2,3,3,3,3}
#define LIST_LL {0,1,2,3,1,0,1,2,1,2,3,2,3,2,1,2,3,0,1,2,3,1,2,3,3,2,3,1,2,3,0,1,2,3}
#define LIST_CG {0,1,10,35,84,93,102,129,174,219,294,399,504,651,676,721,796,901,926,1001,1126,1301,1406,1581,1826,1875,1980,2127,2232,2407,2652,2701,2848,3093}
#define LIST_W  {0,1,10,35,84,87,90,99,114,129,154,189,224,273,278,287,302,323,328,343,368,403,424,459,508,515,530,551,566,591,626,633,654,689}

static const int HT_L1[NT] = LIST_L1;
static const int HT_L2[NT] = LIST_L2;
static const int HT_LL[NT] = LIST_LL;
static const int HT_CG[NT] = LIST_CG;
static const int HT_W[NT]  = LIST_W;

__device__ constexpr int T_L1[NT] = LIST_L1;
__device__ constexpr int T_L2[NT] = LIST_L2;
__device__ constexpr int T_LL[NT] = LIST_LL;
__device__ constexpr int T_CG[NT] = LIST_CG;
__device__ constexpr int T_W[NT]  = LIST_W;

__host__ __device__ constexpr int KLf(int l)   { return 256 - 64 * l; }
__host__ __device__ constexpr int FOFFf(int l) { return l == 0 ? 0 : l == 1 ? 256 : l == 2 ? 832 : 1472; }

static const int H_RBOFF[4] = {0, 8, 14, 18};
static const int H_NMAX[4]  = {8, 6, 4, 2};

// ---------------------------------------------------------------------------
// Host-built tables uploaded per call (one H2D memcpy node, ~26KB)
// ---------------------------------------------------------------------------
struct Blob {
    float cg[NCG];
    int wj_base[NW], wj_st[NW], wj_a0[NW], wj_na[NW];  // w-output build table
    int inv_off[60], inv_sh[60], inv_rb[60];           // invariant combo table
};

__device__ Blob g_blob;
__device__ float g_feats[(size_t)NATOM_MAX * FSTRIDE];   // feats, then mp output
__device__ float g_ef[(size_t)NATOM_MAX * FSTRIDE];      // embedded feats
__device__ float g_cemb[NATOM_MAX * 32];
__device__ int   g_counts[NATOM_MAX];
__device__ int   g_cursor[NATOM_MAX];
__device__ int   g_offsets[NATOM_MAX + 1];
__device__ int   g_sorted[NPAIR_MAX];

// ---------------------------------------------------------------------------
// center embedding: g_cemb[n,c] = emb_table[species[n], c]
// ---------------------------------------------------------------------------
__global__ void cemb_kernel(const float* __restrict__ tab, const int* __restrict__ sp, int natoms) {
    int i = blockIdx.x * blockDim.x + threadIdx.x;
    if (i < natoms * 32) g_cemb[i] = tab[sp[i >> 5] * 32 + (i & 31)];
}

// ---------------------------------------------------------------------------
// counting sort of pairs by center (order within a center nondeterministic;
// fine under tolerance since only float-sum order changes)
// ---------------------------------------------------------------------------
__global__ void zero_kernel(int natoms) {
    int i = blockIdx.x * blockDim.x + threadIdx.x;
    if (i < natoms) { g_counts[i] = 0; g_cursor[i] = 0; }
}
__global__ void hist_kernel(const int* __restrict__ centers, int np) {
    int p = blockIdx.x * blockDim.x + threadIdx.x;
    if (p < np) atomicAdd(&g_counts[centers[p]], 1);
}
__global__ void scan_kernel(int natoms) {  // 1 block, 1024 threads, natoms <= 5120
    __shared__ int ssum[1024];
    int t = threadIdx.x;
    int loc[5]; int s = 0;
#pragma unroll
    for (int i = 0; i < 5; i++) {
        int idx = t * 5 + i;
        loc[i] = s;
        int v = (idx < natoms) ? g_counts[idx] : 0;
        s += v;
    }
    ssum[t] = s;
    __syncthreads();
    for (int off = 1; off < 1024; off <<= 1) {
        int v = (t >= off) ? ssum[t - off] : 0;
        __syncthreads();
        ssum[t] += v;
        __syncthreads();
    }
    int pre = (t > 0) ? ssum[t - 1] : 0;
#pragma unroll
    for (int i = 0; i < 5; i++) {
        int idx = t * 5 + i;
        if (idx <= natoms) g_offsets[idx] = pre + loc[i];
    }
}
__global__ void rank_kernel(const int* __restrict__ centers, int np) {
    int p = blockIdx.x * blockDim.x + threadIdx.x;
    if (p < np) {
        int c = centers[p];
        int r = atomicAdd(&g_cursor[c], 1);
        g_sorted[g_offsets[c] + r] = p;
    }
}

// ---------------------------------------------------------------------------
// invariant MP, gather form: 1 block/center, thread = (combo subset) x channel.
// feats[c, l, m, n*32+ch] = 0.01 * sum_pairs sh[l,m] * rb[l,n] * emb[nbr, ch]
// 60 combos (l,m,n) split 15 per warp; ch = lane. Writes ALL 1920 -> no memset.
// ---------------------------------------------------------------------------
__global__ void __launch_bounds__(128) inv_kernel(
    const float* __restrict__ sh, const float* __restrict__ rb,
    const int* __restrict__ neighbors, int natoms) {
    __shared__ float s_sh[16], s_rb[20], s_emb[32];
    int c = blockIdx.x;
    int tid = threadIdx.x, warp = tid >> 5, lane = tid & 31;
    int offj[15], shi[15], rbi[15];
#pragma unroll
    for (int ii = 0; ii < 15; ii++) {
        int j = warp + 4 * ii;
        offj[ii] = g_blob.inv_off[j];
        shi[ii]  = g_blob.inv_sh[j];
        rbi[ii]  = g_blob.inv_rb[j];
    }
    float acc[15];
#pragma unroll
    for (int ii = 0; ii < 15; ii++) acc[ii] = 0.f;

    int beg = g_offsets[c], end = g_offsets[c + 1];
    for (int i = beg; i < end; i++) {
        int p = g_sorted[i];
        __syncthreads();
        if (tid < 16)      s_sh[tid] = sh[p * 16 + tid];
        else if (tid < 36) s_rb[tid - 16] = rb[p * 20 + (tid - 16)];
        else if (tid < 68) {
            int nbr = neighbors[p];
            s_emb[tid - 36] = g_cemb[nbr * 32 + (tid - 36)];
        }
        __syncthreads();
        float e = s_emb[lane];
#pragma unroll
        for (int ii = 0; ii < 15; ii++) acc[ii] += s_sh[shi[ii]] * s_rb[rbi[ii]] * e;
    }
    float* fb = g_feats + (size_t)c * FSTRIDE;
#pragma unroll
    for (int ii = 0; ii < 15; ii++) fb[offj[ii] + lane] = 0.01f * acc[ii];  // 0.1 nu * 0.1 mp
}

// ---------------------------------------------------------------------------
// in-place CG tensor product: feat += 0.1 * TP(feat, feat). Pointwise in (atom,k).
// LV = 3 - band; band LV only involves triples with all l <= LV. CG in smem.
// ---------------------------------------------------------------------------
template <int LV>
__global__ void __launch_bounds__(128) tp_kernel(int natoms) {
    __shared__ float s_cg[NCG];
    for (int i = threadIdx.x; i < NCG; i += 128) s_cg[i] = g_blob.cg[i];
    __syncthreads();
    int t = blockIdx.x * 128 + threadIdx.x;
    int atom = t >> 5;
    if (atom >= natoms) return;
    constexpr int MM = (LV + 1) * (LV + 1);
    constexpr int KBASE = 64 * (3 - LV);
    int k = KBASE + ((t & 31) << 1);
    float* fb = g_feats + (size_t)atom * FSTRIDE;

    float A0[MM], A1[MM], c0[MM], c1[MM];
#pragma unroll
    for (int l = 0; l <= LV; l++)
#pragma unroll
        for (int m = 0; m < 2 * l + 1; m++) {
            float2 v = *reinterpret_cast<const float2*>(&fb[FOFFf(l) + m * KLf(l) + k]);
            A0[l * l + m] = v.x;
            A1[l * l + m] = v.y;
        }
#pragma unroll
    for (int i = 0; i < MM; i++) { c0[i] = 0.f; c1[i] = 0.f; }

#pragma unroll
    for (int tt = 0; tt < NT; tt++) {
        if (T_L1[tt] > LV || T_L2[tt] > LV || T_LL[tt] > LV) continue;
        const int l1 = T_L1[tt], l2 = T_L2[tt], L = T_LL[tt];
#pragma unroll
        for (int a = 0; a < 2 * l1 + 1; a++)
#pragma unroll
            for (int b = 0; b < 2 * l2 + 1; b++) {
                float p0 = A0[l1 * l1 + a] * A0[l2 * l2 + b];
                float p1 = A1[l1 * l1 + a] * A1[l2 * l2 + b];
#pragma unroll
                for (int M = 0; M < 2 * L + 1; M++) {
                    float cc = s_cg[T_CG[tt] + (a * (2 * l2 + 1) + b) * (2 * L + 1) + M];
                    c0[L * L + M] += cc * p0;
                    c1[L * L + M] += cc * p1;
                }
            }
    }
#pragma unroll
    for (int l = 0; l <= LV; l++)
#pragma unroll
        for (int m = 0; m < 2 * l + 1; m++) {
            int i = l * l + m;
            float2 v;
            v.x = A0[i] + 0.1f * c0[i];
            v.y = A1[i] + 0.1f * c1[i];
            *reinterpret_cast<float2*>(&fb[FOFFf(l) + m * KLf(l) + k]) = v;
        }
}

// ---------------------------------------------------------------------------
// embed: g_ef[n,i] = g_feats[n,i] * cemb[n, i%32]
// ---------------------------------------------------------------------------
__global__ void embed_kernel(int natoms) {
    __shared__ float s_e[32];
    int atomI = blockIdx.x;
    if (threadIdx.x < 32) s_e[threadIdx.x] = g_cemb[atomI * 32 + threadIdx.x];
    __syncthreads();
    const float* fb = g_feats + (size_t)atomI * FSTRIDE;
    float* eb = g_ef + (size_t)atomI * FSTRIDE;
    for (int i = threadIdx.x; i < FSTRIDE; i += blockDim.x) eb[i] = fb[i] * s_e[i & 31];
}

// ---------------------------------------------------------------------------
// equivariant MP, gather form: 1 block/center; per pair build w[b,M] (shared),
// gather ef[nbr], accumulate per-band in registers, single write at end.
// Band (64 ch) rotated across warps/SMSPs by (warp + center) & 3.
// Triple active for band LV iff l2<=LV && L<=LV (l1 free).
// ---------------------------------------------------------------------------
template <int LV>
__device__ __forceinline__ void eq_acc(const float* __restrict__ efn, const float* s_w,
                                       int k, float* a0, float* a1) {
    float f0[(LV + 1) * (LV + 1)], f1[(LV + 1) * (LV + 1)];
#pragma unroll
    for (int l = 0; l <= LV; l++)
#pragma unroll
        for (int b = 0; b < 2 * l + 1; b++) {
            float2 v = *reinterpret_cast<const float2*>(&efn[FOFFf(l) + b * KLf(l) + k]);
            f0[l * l + b] = v.x;
            f1[l * l + b] = v.y;
        }
#pragma unroll
    for (int tt = 0; tt < NT; tt++) {
        if (T_L2[tt] > LV || T_LL[tt] > LV) continue;
        const int l2 = T_L2[tt], L = T_LL[tt];
#pragma unroll
        for (int b = 0; b < 2 * l2 + 1; b++) {
            float fb0 = f0[l2 * l2 + b], fb1 = f1[l2 * l2 + b];
#pragma unroll
            for (int M = 0; M < 2 * L + 1; M++) {
                float wv = s_w[T_W[tt] + b * (2 * L + 1) + M];
                a0[L * L + M] += wv * fb0;
                a1[L * L + M] += wv * fb1;
            }
        }
    }
}

template <int LV>
__device__ __forceinline__ void eq_write(float* __restrict__ mpb, int k,
                                         const float* a0, const float* a1) {
#pragma unroll
    for (int L = 0; L <= LV; L++)
#pragma unroll
        for (int M = 0; M < 2 * L + 1; M++) {
            float2 v;
            v.x = 0.1f * a0[L * L + M];
            v.y = 0.1f * a1[L * L + M];
            *reinterpret_cast<float2*>(&mpb[FOFFf(L) + M * KLf(L) + k]) = v;
        }
}

__global__ void __launch_bounds__(128) eq_kernel(
    const float* __restrict__ sh, const float* __restrict__ rb,
    const int* __restrict__ neighbors, int natoms) {
    __shared__ float s_edge[16];
    __shared__ float s_w[NW];
    int c = blockIdx.x;
    int tid = threadIdx.x, warp = tid >> 5, lane = tid & 31;
    int bk = (warp + c) & 3;          // band index; LV = 3 - bk
    int k = bk * 64 + lane * 2;
    float a0[16], a1[16];
#pragma unroll
    for (int i = 0; i < 16; i++) { a0[i] = 0.f; a1[i] = 0.f; }

    int beg = g_offsets[c], end = g_offsets[c + 1];
    for (int i = beg; i < end; i++) {
        int p = g_sorted[i];
        __syncthreads();
        if (tid < 16) {
            int l = (tid >= 9) ? 3 : (tid >= 4) ? 2 : (tid >= 1) ? 1 : 0;
            int rboff = (l == 3) ? 18 : (l == 2) ? 14 : (l == 1) ? 8 : 0;
            int rbsz = 8 - 2 * l;
            float rs = 0.f;
            for (int n = 0; n < rbsz; n++) rs += rb[p * 20 + rboff + n];
            s_edge[tid] = 0.1f * sh[p * 16 + tid] * rs;   // nu-scaled
        }
        __syncthreads();
        for (int j = tid; j < NW; j += 128) {
            int base = g_blob.wj_base[j], st = g_blob.wj_st[j];
            int av = g_blob.wj_a0[j], na = g_blob.wj_na[j];
            float s = 0.f;
            for (int a = 0; a < na; a++) s += s_edge[av + a] * g_blob.cg[base + a * st];
            s_w[j] = s;
        }
        __syncthreads();
        int nbr = neighbors[p];
        const float* efn = g_ef + (size_t)nbr * FSTRIDE;
        if (bk == 0)      eq_acc<3>(efn, s_w, k, a0, a1);
        else if (bk == 1) eq_acc<2>(efn, s_w, k, a0, a1);
        else if (bk == 2) eq_acc<1>(efn, s_w, k, a0, a1);
        else              eq_acc<0>(efn, s_w, k, a0, a1);
    }
    float* mpb = g_feats + (size_t)c * FSTRIDE;   // overwrite feats with mp output
    if (bk == 0)      eq_write<3>(mpb, k, a0, a1);
    else if (bk == 1) eq_write<2>(mpb, k, a0, a1);
    else if (bk == 2) eq_write<1>(mpb, k, a0, a1);
    else              eq_write<0>(mpb, k, a0, a1);
}

// ---------------------------------------------------------------------------
// energy: out[n] = sum_k feats[n,0,k] * cemb[n,k%32] * w[k] + b   (embed folded)
// ---------------------------------------------------------------------------
__global__ void energy_kernel(const float* __restrict__ we, const float* __restrict__ be,
                              float* __restrict__ out, int natoms) {
    int atomI = blockIdx.x * 4 + (threadIdx.x >> 5);
    int lane = threadIdx.x & 31;
    if (atomI >= natoms) return;
    float e = g_cemb[atomI * 32 + lane];
    const float* fb = g_feats + (size_t)atomI * FSTRIDE;
    float s = 0.f;
#pragma unroll
    for (int kk = 0; kk < 8; kk++) s += fb[kk * 32 + lane] * we[kk * 32 + lane];
    s *= e;
#pragma unroll
    for (int o = 16; o > 0; o >>= 1) s += __shfl_xor_sync(0xffffffffu, s, o);
    if (lane == 0) out[atomI] = s + be[0];
}

// ---------------------------------------------------------------------------
// host: bit-exact numpy legacy RandomState(0).randn (rk_seed MT19937 + polar
// gauss with cache), and index-table construction. Recomputed every call.
// ---------------------------------------------------------------------------
static uint32_t s_mt[624];
static int s_mti;

static uint32_t mt_next() {
    if (s_mti >= 624) {
        for (int kk = 0; kk < 624; kk++) {
            uint32_t y = (s_mt[kk] & 0x80000000u) | (s_mt[(kk + 1) % 624] & 0x7fffffffu);
            s_mt[kk] = s_mt[(kk + 397) % 624] ^ (y >> 1) ^ ((y & 1u) ? 2567483615u : 0u);
        }
        s_mti = 0;
    }
    uint32_t y = s_mt[s_mti++];
    y ^= y >> 11;
    y ^= (y << 7) & 2636928640u;
    y ^= (y << 15) & 4022730752u;
    y ^= y >> 18;
    return y;
}
static double mt_double() {
    uint32_t a = mt_next() >> 5, b = mt_next() >> 6;
    return (a * 67108864.0 + b) / 9007199254740992.0;
}

static void build_blob(Blob& B) {
    // rk_seed(0)
    uint32_t seed = 0;
    for (int pos = 0; pos < 624; pos++) {
        s_mt[pos] = seed;
        seed = 1812433253u * (seed ^ (seed >> 30)) + (uint32_t)pos + 1u;
    }
    s_mti = 624;
    int has_g = 0;
    double gcache = 0.0;
    for (int t = 0; t < NCG; t++) {
        double g;
        if (has_g) { g = gcache; has_g = 0; }
        else {
            double x1, x2, r2, f;
            do {
                x1 = 2.0 * mt_double() - 1.0;
                x2 = 2.0 * mt_double() - 1.0;
                r2 = x1 * x1 + x2 * x2;
            } while (r2 >= 1.0 || r2 == 0.0);
            f = sqrt(-2.0 * log(r2) / r2);
            gcache = f * x1;
            has_g = 1;
            g = f * x2;
        }
        B.cg[t] = (float)(g * 0.2);
    }
    // w-output build table: w[j] = sum_a edge[a0+a] * cg[base + a*st]
    for (int tt = 0; tt < NT; tt++) {
        int l1 = HT_L1[tt], l2 = HT_L2[tt], L = HT_LL[tt];
        for (int b = 0; b < 2 * l2 + 1; b++)
            for (int M = 0; M < 2 * L + 1; M++) {
                int j = HT_W[tt] + b * (2 * L + 1) + M;
                B.wj_base[j] = HT_CG[tt] + b * (2 * L + 1) + M;
                B.wj_st[j]   = (2 * l2 + 1) * (2 * L + 1);
                B.wj_a0[j]   = l1 * l1;
                B.wj_na[j]   = 2 * l1 + 1;
            }
    }
    // invariant combo table: (l, m, n)
    int j = 0;
    for (int l = 0; l < 4; l++)
        for (int m = 0; m < 2 * l + 1; m++)
            for (int n = 0; n < H_NMAX[l]; n++) {
                B.inv_off[j] = FOFFf(l) + m * KLf(l) + n * 32;
                B.inv_sh[j]  = l * l + m;
                B.inv_rb[j]  = H_RBOFF[l] + n;
                j++;
            }
}

static Blob h_blob;  // static storage: must outlive graph replays (memcpy node source)

// ---------------------------------------------------------------------------
extern "C" void kernel_launch(void* const* d_in, const int* in_sizes, int n_in,
                              void* d_out, int out_size) {
    const float* sh        = (const float*)d_in[0];
    const float* rb        = (const float*)d_in[1];
    const float* emb_table = (const float*)d_in[2];
    const float* w_energy  = (const float*)d_in[3];
    const float* b_energy  = (const float*)d_in[4];
    const int*   species   = (const int*)d_in[5];
    const int*   centers   = (const int*)d_in[6];
    const int*   neighbors = (const int*)d_in[7];
    int natoms = in_sizes[5];
    int np     = in_sizes[6];
    if (natoms > NATOM_MAX) natoms = NATOM_MAX;
    if (np > NPAIR_MAX)     np = NPAIR_MAX;
    float* out = (float*)d_out;

    build_blob(h_blob);  // recomputed every call (deterministic); copied every call
    cudaMemcpyToSymbolAsync(g_blob, &h_blob, sizeof(Blob), 0, cudaMemcpyHostToDevice, 0);

    // embeddings + counting sort of pairs by center
    cemb_kernel<<<(natoms * 32 + 255) / 256, 256>>>(emb_table, species, natoms);
    zero_kernel<<<(natoms + 255) / 256, 256>>>(natoms);
    hist_kernel<<<(np + 255) / 256, 256>>>(centers, np);
    scan_kernel<<<1, 1024>>>(natoms);
    rank_kernel<<<(np + 255) / 256, 256>>>(centers, np);

    // invariant MP (gather) -> feats
    inv_kernel<<<natoms, 128>>>(sh, rb, neighbors, natoms);

    // cg_iterate #1 (in-place TP on feats), per band
    int tpg = (natoms * 32 + 127) / 128;
    tp_kernel<3><<<tpg, 128>>>(natoms);
    tp_kernel<2><<<tpg, 128>>>(natoms);
    tp_kernel<1><<<tpg, 128>>>(natoms);
    tp_kernel<0><<<tpg, 128>>>(natoms);

    // embed centers -> ef
    embed_kernel<<<natoms, 256>>>(natoms);

    // equivariant MP (gather): reads ef, overwrites feats with mp output
    eq_kernel<<<natoms, 128>>>(sh, rb, neighbors, natoms);

    // cg_iterate #2
    tp_kernel<3><<<tpg, 128>>>(natoms);
    tp_kernel<2><<<tpg, 128>>>(natoms);
    tp_kernel<1><<<tpg, 128>>>(natoms);
    tp_kernel<0><<<tpg, 128>>>(natoms);

    // final embed folded into energy readout
    energy_kernel<<<(natoms + 3) / 4, 128>>>(w_energy, b_energy, out, natoms);
}

// round 7
// speedup vs baseline: 1.2611x; 1.2611x over previous
#include <cuda_runtime.h>
#include <stdint.h>
#include <math.h>
#include <string.h>

// ---------------------------------------------------------------------------
// Constants: L_MAX=3, N_MAX_L=[8,6,4,2], C=32, K_L=[256,192,128,64]
// feature layout per atom (1920 floats): [l0:1x256][l1:3x192][l2:5x128][l3:7x64]
// element (l,m,k) at FOFF[l] + m*KL[l] + k
// ---------------------------------------------------------------------------
#define NT        34
#define NCG       3436
#define NW        738
#define WPAD      740
#define NATOM_MAX 5000
#define NPAIR_MAX 100000
#define FSTRIDE   1920

#define LIST_L1 {0,0,0,0,1,1,1,1,1,1,1,1,1,2,2,2,2,2,2,2,2,2,2,2,3,3,3,3,3,3,3,3,3,3}
#define LIST_L2 {0,1,2,3,0,1,1,1,2,2,2,3,3,0,1,1,1,2,2,2,2,3,3,3,0,1,1,2,2,2,3,3,3,3}
#define LIST_LL {0,1,2,3,1,0,1,2,1,2,3,2,3,2,1,2,3,0,1,2,3,1,2,3,3,2,3,1,2,3,0,1,2,3}
#define LIST_CG {0,1,10,35,84,93,102,129,174,219,294,399,504,651,676,721,796,901,926,1001,1126,1301,1406,1581,1826,1875,1980,2127,2232,2407,2652,2701,2848,3093}
#define LIST_W  {0,1,10,35,84,87,90,99,114,129,154,189,224,273,278,287,302,323,328,343,368,403,424,459,508,515,530,551,566,591,626,633,654,689}

static const int HT_L1[NT] = LIST_L1;
static const int HT_L2[NT] = LIST_L2;
static const int HT_LL[NT] = LIST_LL;
static const int HT_CG[NT] = LIST_CG;
static const int HT_W[NT]  = LIST_W;

__device__ constexpr int T_L1[NT] = LIST_L1;
__device__ constexpr int T_L2[NT] = LIST_L2;
__device__ constexpr int T_LL[NT] = LIST_LL;
__device__ constexpr int T_CG[NT] = LIST_CG;
__device__ constexpr int T_W[NT]  = LIST_W;

__host__ __device__ constexpr int KLf(int l)   { return 256 - 64 * l; }
__host__ __device__ constexpr int FOFFf(int l) { return l == 0 ? 0 : l == 1 ? 256 : l == 2 ? 832 : 1472; }

static const int H_RBOFF[4] = {0, 8, 14, 18};
static const int H_NMAX[4]  = {8, 6, 4, 2};

typedef unsigned long long ull;

// packed fp32x2 math (sm_10x; FFMA2 only reachable via PTX)
__device__ __forceinline__ ull f2_fma(ull a, ull b, ull c) {
    ull d; asm("fma.rn.f32x2 %0, %1, %2, %3;" : "=l"(d) : "l"(a), "l"(b), "l"(c)); return d;
}
__device__ __forceinline__ ull f2_mul(ull a, ull b) {
    ull d; asm("mul.rn.f32x2 %0, %1, %2;" : "=l"(d) : "l"(a), "l"(b)); return d;
}
__device__ __forceinline__ ull f2_dup(float x) {
    ull d; unsigned xi = __float_as_uint(x);
    asm("mov.b64 %0, {%1, %1};" : "=l"(d) : "r"(xi)); return d;
}

// ---------------------------------------------------------------------------
struct Blob {
    float cg[NCG];
    int wj_base[NW], wj_st[NW], wj_a0[NW], wj_na[NW];
    int inv_off[60], inv_sh[60], inv_rb[60];
};

__device__ Blob  g_blob;
__device__ float g_feats[(size_t)NATOM_MAX * FSTRIDE];
__device__ float g_ef[(size_t)NATOM_MAX * FSTRIDE];
__device__ float g_wall[(size_t)NPAIR_MAX * WPAD];     // per-pair w[738] (padded)
__device__ float g_cemb[NATOM_MAX * 32];
__device__ int   g_counts[NATOM_MAX];
__device__ int   g_cursor[NATOM_MAX];
__device__ int   g_offsets[NATOM_MAX + 1];
__device__ int   g_sorted[NPAIR_MAX];

// ---------------------------------------------------------------------------
__global__ void cemb_kernel(const float* __restrict__ tab, const int* __restrict__ sp, int natoms) {
    int i = blockIdx.x * blockDim.x + threadIdx.x;
    if (i < natoms * 32) g_cemb[i] = tab[sp[i >> 5] * 32 + (i & 31)];
}

// ---------------------------------------------------------------------------
// counting sort of pairs by center
// ---------------------------------------------------------------------------
__global__ void zero_kernel(int natoms) {
    int i = blockIdx.x * blockDim.x + threadIdx.x;
    if (i < natoms) { g_counts[i] = 0; g_cursor[i] = 0; }
}
__global__ void hist_kernel(const int* __restrict__ centers, int np) {
    int p = blockIdx.x * blockDim.x + threadIdx.x;
    if (p < np) atomicAdd(&g_counts[centers[p]], 1);
}
__global__ void scan_kernel(int natoms) {
    __shared__ int ssum[1024];
    int t = threadIdx.x;
    int loc[5]; int s = 0;
#pragma unroll
    for (int i = 0; i < 5; i++) {
        int idx = t * 5 + i;
        loc[i] = s;
        int v = (idx < natoms) ? g_counts[idx] : 0;
        s += v;
    }
    ssum[t] = s;
    __syncthreads();
    for (int off = 1; off < 1024; off <<= 1) {
        int v = (t >= off) ? ssum[t - off] : 0;
        __syncthreads();
        ssum[t] += v;
        __syncthreads();
    }
    int pre = (t > 0) ? ssum[t - 1] : 0;
#pragma unroll
    for (int i = 0; i < 5; i++) {
        int idx = t * 5 + i;
        if (idx <= natoms) g_offsets[idx] = pre + loc[i];
    }
}
__global__ void rank_kernel(const int* __restrict__ centers, int np) {
    int p = blockIdx.x * blockDim.x + threadIdx.x;
    if (p < np) {
        int c = centers[p];
        int r = atomicAdd(&g_cursor[c], 1);
        g_sorted[g_offsets[c] + r] = p;
    }
}

// ---------------------------------------------------------------------------
// pair-parallel edge-weight build: g_wall[p][j] for all 738 w outputs.
// w[j] = sum_a edge[l1, a] * cg[base + a*st];  edge = 0.1 * sh * rb_sum(l)
// ---------------------------------------------------------------------------
#define PPB 16
__global__ void __launch_bounds__(128) wcomp_kernel(
    const float* __restrict__ sh, const float* __restrict__ rb, int np) {
    __shared__ float s_cg[NCG];
    __shared__ int s_base[NW], s_st[NW], s_a0[NW], s_na[NW];
    __shared__ float s_edge[4][16];
    int tid = threadIdx.x;
    for (int i = tid; i < NCG; i += 128) s_cg[i] = g_blob.cg[i];
    for (int i = tid; i < NW; i += 128) {
        s_base[i] = g_blob.wj_base[i]; s_st[i] = g_blob.wj_st[i];
        s_a0[i] = g_blob.wj_a0[i];     s_na[i] = g_blob.wj_na[i];
    }
    __syncthreads();
    int warp = tid >> 5, lane = tid & 31;
    for (int pi = warp; pi < PPB; pi += 4) {
        int p = blockIdx.x * PPB + pi;
        if (p >= np) break;
        if (lane < 16) {
            int l = (lane >= 9) ? 3 : (lane >= 4) ? 2 : (lane >= 1) ? 1 : 0;
            int rboff = (l == 3) ? 18 : (l == 2) ? 14 : (l == 1) ? 8 : 0;
            int rbsz = 8 - 2 * l;
            float rs = 0.f;
            for (int n = 0; n < rbsz; n++) rs += rb[(size_t)p * 20 + rboff + n];
            s_edge[warp][lane] = 0.1f * sh[(size_t)p * 16 + lane] * rs;
        }
        __syncwarp();
        float* wp = g_wall + (size_t)p * WPAD;
        for (int j = lane; j < NW; j += 32) {
            int base = s_base[j], st = s_st[j], a0 = s_a0[j], na = s_na[j];
            float s = 0.f;
            for (int a = 0; a < na; a++) s += s_edge[warp][a0 + a] * s_cg[base + a * st];
            wp[j] = s;
        }
        __syncwarp();
    }
}

// ---------------------------------------------------------------------------
// invariant MP, gather form w/ double-buffered register-staged prefetch.
// ---------------------------------------------------------------------------
__global__ void __launch_bounds__(128) inv_kernel(
    const float* __restrict__ sh, const float* __restrict__ rb,
    const int* __restrict__ neighbors, int natoms) {
    __shared__ float s_in[2][68];   // [0:16) sh, [16:36) rb, [36:68) emb
    int c = blockIdx.x;
    int tid = threadIdx.x, warp = tid >> 5, lane = tid & 31;
    int offj[15], shi[15], rbi[15];
#pragma unroll
    for (int ii = 0; ii < 15; ii++) {
        int j = warp + 4 * ii;
        offj[ii] = g_blob.inv_off[j];
        shi[ii]  = g_blob.inv_sh[j];
        rbi[ii]  = g_blob.inv_rb[j];
    }
    float acc[15];
#pragma unroll
    for (int ii = 0; ii < 15; ii++) acc[ii] = 0.f;

    int beg = g_offsets[c], end = g_offsets[c + 1];
    if (beg < end) {
        int p0 = g_sorted[beg];
        if (tid < 16)      s_in[0][tid] = sh[(size_t)p0 * 16 + tid];
        else if (tid < 36) s_in[0][tid] = rb[(size_t)p0 * 20 + (tid - 16)];
        else if (tid < 68) s_in[0][tid] = g_cemb[neighbors[p0] * 32 + (tid - 36)];
    }
    __syncthreads();
    for (int i = beg; i < end; i++) {
        int cur = (i - beg) & 1;
        float nst = 0.f;
        bool more = (i + 1 < end);
        if (more && tid < 68) {
            int pn = g_sorted[i + 1];
            if (tid < 16)      nst = sh[(size_t)pn * 16 + tid];
            else if (tid < 36) nst = rb[(size_t)pn * 20 + (tid - 16)];
            else               nst = g_cemb[neighbors[pn] * 32 + (tid - 36)];
        }
        float e = s_in[cur][36 + lane];
#pragma unroll
        for (int ii = 0; ii < 15; ii++)
            acc[ii] += s_in[cur][shi[ii]] * s_in[cur][16 + rbi[ii]] * e;
        if (more && tid < 68) s_in[cur ^ 1][tid] = nst;
        __syncthreads();
    }
    float* fb = g_feats + (size_t)c * FSTRIDE;
#pragma unroll
    for (int ii = 0; ii < 15; ii++) fb[offj[ii] + lane] = 0.01f * acc[ii];
}

// ---------------------------------------------------------------------------
// in-place CG tensor product, FFMA2 path (bands LV=3,2): feat += 0.1*TP(feat,feat)
// ---------------------------------------------------------------------------
template <int LV>
__global__ void __launch_bounds__(128) tp2_kernel(int natoms) {
    __shared__ __align__(16) float s_cg2[2 * NCG];
    for (int i = threadIdx.x; i < NCG; i += 128) {
        float v = g_blob.cg[i];
        *reinterpret_cast<float2*>(&s_cg2[2 * i]) = make_float2(v, v);
    }
    __syncthreads();
    int t = blockIdx.x * 128 + threadIdx.x;
    int atom = t >> 5;
    if (atom >= natoms) return;
    constexpr int MM = (LV + 1) * (LV + 1);
    constexpr int KBASE = 64 * (3 - LV);
    int k = KBASE + ((t & 31) << 1);
    float* fb = g_feats + (size_t)atom * FSTRIDE;

    ull A[MM], acc[MM];
#pragma unroll
    for (int l = 0; l <= LV; l++)
#pragma unroll
        for (int m = 0; m < 2 * l + 1; m++)
            A[l * l + m] = *reinterpret_cast<const ull*>(&fb[FOFFf(l) + m * KLf(l) + k]);
#pragma unroll
    for (int i = 0; i < MM; i++) acc[i] = 0ull;

#pragma unroll
    for (int tt = 0; tt < NT; tt++) {
        if (T_L1[tt] > LV || T_L2[tt] > LV || T_LL[tt] > LV) continue;
        const int l1 = T_L1[tt], l2 = T_L2[tt], L = T_LL[tt];
#pragma unroll
        for (int a = 0; a < 2 * l1 + 1; a++)
#pragma unroll
            for (int b = 0; b < 2 * l2 + 1; b++) {
                ull p = f2_mul(A[l1 * l1 + a], A[l2 * l2 + b]);
#pragma unroll
                for (int M = 0; M < 2 * L + 1; M++) {
                    ull c2 = *reinterpret_cast<const ull*>(
                        &s_cg2[2 * (T_CG[tt] + (a * (2 * l2 + 1) + b) * (2 * L + 1) + M)]);
                    acc[L * L + M] = f2_fma(c2, p, acc[L * L + M]);
                }
            }
    }
    ull sc = f2_dup(0.1f);
#pragma unroll
    for (int l = 0; l <= LV; l++)
#pragma unroll
        for (int m = 0; m < 2 * l + 1; m++) {
            int i = l * l + m;
            ull v = f2_fma(sc, acc[i], A[i]);
            *reinterpret_cast<ull*>(&fb[FOFFf(l) + m * KLf(l) + k]) = v;
        }
}

// scalar TP for tiny bands (LV=1: 34 terms, LV=0: 1 term); cg via __ldg
template <int LV>
__global__ void __launch_bounds__(128) tp_small_kernel(int natoms) {
    int t = blockIdx.x * 128 + threadIdx.x;
    int atom = t >> 5;
    if (atom >= natoms) return;
    constexpr int MM = (LV + 1) * (LV + 1);
    constexpr int KBASE = 64 * (3 - LV);
    int k = KBASE + ((t & 31) << 1);
    float* fb = g_feats + (size_t)atom * FSTRIDE;
    float A0[MM], A1[MM], c0[MM], c1[MM];
#pragma unroll
    for (int l = 0; l <= LV; l++)
#pragma unroll
        for (int m = 0; m < 2 * l + 1; m++) {
            float2 v = *reinterpret_cast<const float2*>(&fb[FOFFf(l) + m * KLf(l) + k]);
            A0[l * l + m] = v.x; A1[l * l + m] = v.y;
        }
#pragma unroll
    for (int i = 0; i < MM; i++) { c0[i] = 0.f; c1[i] = 0.f; }
#pragma unroll
    for (int tt = 0; tt < NT; tt++) {
        if (T_L1[tt] > LV || T_L2[tt] > LV || T_LL[tt] > LV) continue;
        const int l1 = T_L1[tt], l2 = T_L2[tt], L = T_LL[tt];
#pragma unroll
        for (int a = 0; a < 2 * l1 + 1; a++)
#pragma unroll
            for (int b = 0; b < 2 * l2 + 1; b++) {
                float p0 = A0[l1 * l1 + a] * A0[l2 * l2 + b];
                float p1 = A1[l1 * l1 + a] * A1[l2 * l2 + b];
#pragma unroll
                for (int M = 0; M < 2 * L + 1; M++) {
                    float cc = __ldg(&g_blob.cg[T_CG[tt] + (a * (2 * l2 + 1) + b) * (2 * L + 1) + M]);
                    c0[L * L + M] += cc * p0;
                    c1[L * L + M] += cc * p1;
                }
            }
    }
#pragma unroll
    for (int l = 0; l <= LV; l++)
#pragma unroll
        for (int m = 0; m < 2 * l + 1; m++) {
            int i = l * l + m;
            float2 v;
            v.x = A0[i] + 0.1f * c0[i];
            v.y = A1[i] + 0.1f * c1[i];
            *reinterpret_cast<float2*>(&fb[FOFFf(l) + m * KLf(l) + k]) = v;
        }
}

// ---------------------------------------------------------------------------
// embed: g_ef[n,i] = g_feats[n,i] * cemb[n, i%32]
// ---------------------------------------------------------------------------
__global__ void embed_kernel(int natoms) {
    __shared__ float s_e[32];
    int atomI = blockIdx.x;
    if (threadIdx.x < 32) s_e[threadIdx.x] = g_cemb[atomI * 32 + threadIdx.x];
    __syncthreads();
    const float* fb = g_feats + (size_t)atomI * FSTRIDE;
    float* eb = g_ef + (size_t)atomI * FSTRIDE;
    for (int i = threadIdx.x; i < FSTRIDE; i += blockDim.x) eb[i] = fb[i] * s_e[i & 31];
}

// ---------------------------------------------------------------------------
// equivariant MP, gather form: per-pair w precomputed (g_wall); double-buffered
// duplicated-w smem; FFMA2 accumulation; band-per-warp rotated across SMSPs.
// ---------------------------------------------------------------------------
template <int LV>
__device__ __forceinline__ void eq_acc2(const float* __restrict__ efn,
                                        const float* __restrict__ sw2,
                                        int k, ull* acc) {
    ull f[(LV + 1) * (LV + 1)];
#pragma unroll
    for (int l = 0; l <= LV; l++)
#pragma unroll
        for (int b = 0; b < 2 * l + 1; b++)
            f[l * l + b] = *reinterpret_cast<const ull*>(&efn[FOFFf(l) + b * KLf(l) + k]);
#pragma unroll
    for (int tt = 0; tt < NT; tt++) {
        if (T_L2[tt] > LV || T_LL[tt] > LV) continue;
        const int l2 = T_L2[tt], L = T_LL[tt];
#pragma unroll
        for (int b = 0; b < 2 * l2 + 1; b++) {
            ull fb = f[l2 * l2 + b];
#pragma unroll
            for (int M = 0; M < 2 * L + 1; M++) {
                ull w2 = *reinterpret_cast<const ull*>(
                    &sw2[2 * (T_W[tt] + b * (2 * L + 1) + M)]);
                acc[L * L + M] = f2_fma(w2, fb, acc[L * L + M]);
            }
        }
    }
}

template <int LV>
__device__ __forceinline__ void eq_write2(float* __restrict__ mpb, int k, const ull* acc) {
#pragma unroll
    for (int L = 0; L <= LV; L++)
#pragma unroll
        for (int M = 0; M < 2 * L + 1; M++) {
            ull v = acc[L * L + M];
            float2 vf = *reinterpret_cast<float2*>(&v);
            float2 o; o.x = 0.1f * vf.x; o.y = 0.1f * vf.y;
            *reinterpret_cast<float2*>(&mpb[FOFFf(L) + M * KLf(L) + k]) = o;
        }
}

__global__ void __launch_bounds__(128) eq_kernel(const int* __restrict__ neighbors, int natoms) {
    __shared__ __align__(16) float s_w2[2][2 * NW];
    int c = blockIdx.x;
    int tid = threadIdx.x, warp = tid >> 5, lane = tid & 31;
    int bk = (warp + c) & 3;          // band; LV = 3 - bk
    int k = bk * 64 + lane * 2;
    ull acc[16];
#pragma unroll
    for (int i = 0; i < 16; i++) acc[i] = 0ull;

    int beg = g_offsets[c], end = g_offsets[c + 1];
    int nbr_cur = 0;
    if (beg < end) {
        int p0 = g_sorted[beg];
        nbr_cur = neighbors[p0];
        const float* wp = g_wall + (size_t)p0 * WPAD;
#pragma unroll
        for (int jj = 0; jj < 6; jj++) {
            int j = tid + jj * 128;
            if (j < NW) {
                float v = wp[j];
                *reinterpret_cast<float2*>(&s_w2[0][2 * j]) = make_float2(v, v);
            }
        }
    }
    __syncthreads();
    for (int i = beg; i < end; i++) {
        int cur = (i - beg) & 1;
        bool more = (i + 1 < end);
        float nst[6];
        int nbr_next = 0;
        if (more) {
            int pn = g_sorted[i + 1];
            nbr_next = neighbors[pn];
            const float* wp = g_wall + (size_t)pn * WPAD;
#pragma unroll
            for (int jj = 0; jj < 6; jj++) {
                int j = tid + jj * 128;
                nst[jj] = (j < NW) ? wp[j] : 0.f;
            }
        }
        const float* efn = g_ef + (size_t)nbr_cur * FSTRIDE;
        const float* sw = s_w2[cur];
        if (bk == 0)      eq_acc2<3>(efn, sw, k, acc);
        else if (bk == 1) eq_acc2<2>(efn, sw, k, acc);
        else if (bk == 2) eq_acc2<1>(efn, sw, k, acc);
        else              eq_acc2<0>(efn, sw, k, acc);
        if (more) {
#pragma unroll
            for (int jj = 0; jj < 6; jj++) {
                int j = tid + jj * 128;
                if (j < NW)
                    *reinterpret_cast<float2*>(&s_w2[cur ^ 1][2 * j]) = make_float2(nst[jj], nst[jj]);
            }
            nbr_cur = nbr_next;
        }
        __syncthreads();
    }
    float* mpb = g_feats + (size_t)c * FSTRIDE;
    if (bk == 0)      eq_write2<3>(mpb, k, acc);
    else if (bk == 1) eq_write2<2>(mpb, k, acc);
    else if (bk == 2) eq_write2<1>(mpb, k, acc);
    else              eq_write2<0>(mpb, k, acc);
}

// ---------------------------------------------------------------------------
// energy: out[n] = sum_k feats[n,0,k] * cemb[n,k%32] * w[k] + b
// ---------------------------------------------------------------------------
__global__ void energy_kernel(const float* __restrict__ we, const float* __restrict__ be,
                              float* __restrict__ out, int natoms) {
    int atomI = blockIdx.x * 4 + (threadIdx.x >> 5);
    int lane = threadIdx.x & 31;
    if (atomI >= natoms) return;
    float e = g_cemb[atomI * 32 + lane];
    const float* fb = g_feats + (size_t)atomI * FSTRIDE;
    float s = 0.f;
#pragma unroll
    for (int kk = 0; kk < 8; kk++) s += fb[kk * 32 + lane] * we[kk * 32 + lane];
    s *= e;
#pragma unroll
    for (int o = 16; o > 0; o >>= 1) s += __shfl_xor_sync(0xffffffffu, s, o);
    if (lane == 0) out[atomI] = s + be[0];
}

// ---------------------------------------------------------------------------
// host: bit-exact numpy legacy RandomState(0).randn + table construction
// ---------------------------------------------------------------------------
static uint32_t s_mt[624];
static int s_mti;
static uint32_t mt_next() {
    if (s_mti >= 624) {
        for (int kk = 0; kk < 624; kk++) {
            uint32_t y = (s_mt[kk] & 0x80000000u) | (s_mt[(kk + 1) % 624] & 0x7fffffffu);
            s_mt[kk] = s_mt[(kk + 397) % 624] ^ (y >> 1) ^ ((y & 1u) ? 2567483615u : 0u);
        }
        s_mti = 0;
    }
    uint32_t y = s_mt[s_mti++];
    y ^= y >> 11;
    y ^= (y << 7) & 2636928640u;
    y ^= (y << 15) & 4022730752u;
    y ^= y >> 18;
    return y;
}
static double mt_double() {
    uint32_t a = mt_next() >> 5, b = mt_next() >> 6;
    return (a * 67108864.0 + b) / 9007199254740992.0;
}

static void build_blob(Blob& B) {
    uint32_t seed = 0;
    for (int pos = 0; pos < 624; pos++) {
        s_mt[pos] = seed;
        seed = 1812433253u * (seed ^ (seed >> 30)) + (uint32_t)pos + 1u;
    }
    s_mti = 624;
    int has_g = 0;
    double gcache = 0.0;
    for (int t = 0; t < NCG; t++) {
        double g;
        if (has_g) { g = gcache; has_g = 0; }
        else {
            double x1, x2, r2, f;
            do {
                x1 = 2.0 * mt_double() - 1.0;
                x2 = 2.0 * mt_double() - 1.0;
                r2 = x1 * x1 + x2 * x2;
            } while (r2 >= 1.0 || r2 == 0.0);
            f = sqrt(-2.0 * log(r2) / r2);
            gcache = f * x1;
            has_g = 1;
            g = f * x2;
        }
        B.cg[t] = (float)(g * 0.2);
    }
    for (int tt = 0; tt < NT; tt++) {
        int l1 = HT_L1[tt], l2 = HT_L2[tt], L = HT_LL[tt];
        for (int b = 0; b < 2 * l2 + 1; b++)
            for (int M = 0; M < 2 * L + 1; M++) {
                int j = HT_W[tt] + b * (2 * L + 1) + M;
                B.wj_base[j] = HT_CG[tt] + b * (2 * L + 1) + M;
                B.wj_st[j]   = (2 * l2 + 1) * (2 * L + 1);
                B.wj_a0[j]   = l1 * l1;
                B.wj_na[j]   = 2 * l1 + 1;
            }
    }
    int j = 0;
    for (int l = 0; l < 4; l++)
        for (int m = 0; m < 2 * l + 1; m++)
            for (int n = 0; n < H_NMAX[l]; n++) {
                B.inv_off[j] = FOFFf(l) + m * KLf(l) + n * 32;
                B.inv_sh[j]  = l * l + m;
                B.inv_rb[j]  = H_RBOFF[l] + n;
                j++;
            }
}

static Blob h_blob;   // static: must outlive graph replays (memcpy node source)

// ---------------------------------------------------------------------------
extern "C" void kernel_launch(void* const* d_in, const int* in_sizes, int n_in,
                              void* d_out, int out_size) {
    const float* sh        = (const float*)d_in[0];
    const float* rb        = (const float*)d_in[1];
    const float* emb_table = (const float*)d_in[2];
    const float* w_energy  = (const float*)d_in[3];
    const float* b_energy  = (const float*)d_in[4];
    const int*   species   = (const int*)d_in[5];
    const int*   centers   = (const int*)d_in[6];
    const int*   neighbors = (const int*)d_in[7];
    int natoms = in_sizes[5];
    int np     = in_sizes[6];
    if (natoms > NATOM_MAX) natoms = NATOM_MAX;
    if (np > NPAIR_MAX)     np = NPAIR_MAX;
    float* out = (float*)d_out;

    build_blob(h_blob);
    cudaMemcpyToSymbolAsync(g_blob, &h_blob, sizeof(Blob), 0, cudaMemcpyHostToDevice, 0);

    // embeddings + counting sort of pairs by center
    cemb_kernel<<<(natoms * 32 + 255) / 256, 256>>>(emb_table, species, natoms);
    zero_kernel<<<(natoms + 255) / 256, 256>>>(natoms);
    hist_kernel<<<(np + 255) / 256, 256>>>(centers, np);
    scan_kernel<<<1, 1024>>>(natoms);
    rank_kernel<<<(np + 255) / 256, 256>>>(centers, np);

    // per-pair edge weights (independent of feats; feeds eq_kernel)
    wcomp_kernel<<<(np + PPB - 1) / PPB, 128>>>(sh, rb, np);

    // invariant MP (gather) -> feats
    inv_kernel<<<natoms, 128>>>(sh, rb, neighbors, natoms);

    // cg_iterate #1
    int tpg = (natoms * 32 + 127) / 128;
    tp2_kernel<3><<<tpg, 128>>>(natoms);
    tp2_kernel<2><<<tpg, 128>>>(natoms);
    tp_small_kernel<1><<<tpg, 128>>>(natoms);
    tp_small_kernel<0><<<tpg, 128>>>(natoms);

    // embed centers -> ef
    embed_kernel<<<natoms, 256>>>(natoms);

    // equivariant MP (gather): reads ef + g_wall, overwrites feats with mp out
    eq_kernel<<<natoms, 128>>>(neighbors, natoms);

    // cg_iterate #2
    tp2_kernel<3><<<tpg, 128>>>(natoms);
    tp2_kernel<2><<<tpg, 128>>>(natoms);
    tp_small_kernel<1><<<tpg, 128>>>(natoms);
    tp_small_kernel<0><<<tpg, 128>>>(natoms);

    // final embed folded into energy readout
    energy_kernel<<<(natoms + 3) / 4, 128>>>(w_energy, b_energy, out, natoms);
}

// round 8
// speedup vs baseline: 1.4795x; 1.1731x over previous
#include <cuda_runtime.h>
#include <stdint.h>
#include <math.h>
#include <string.h>

// ---------------------------------------------------------------------------
// Constants: L_MAX=3, N_MAX_L=[8,6,4,2], C=32, K_L=[256,192,128,64]
// feature layout per atom (1920 floats): [l0:1x256][l1:3x192][l2:5x128][l3:7x64]
// element (l,m,k) at FOFF[l] + m*KL[l] + k
// ---------------------------------------------------------------------------
#define NT        34
#define NCG       3436
#define NATOM_MAX 5000
#define NPAIR_MAX 100000
#define FSTRIDE   1920

#define LIST_L1 {0,0,0,0,1,1,1,1,1,1,1,1,1,2,2,2,2,2,2,2,2,2,2,2,3,3,3,3,3,3,3,3,3,3}
#define LIST_L2 {0,1,2,3,0,1,1,1,2,2,2,3,3,0,1,1,1,2,2,2,2,3,3,3,0,1,1,2,2,2,3,3,3,3}
#define LIST_LL {0,1,2,3,1,0,1,2,1,2,3,2,3,2,1,2,3,0,1,2,3,1,2,3,3,2,3,1,2,3,0,1,2,3}
#define LIST_CG {0,1,10,35,84,93,102,129,174,219,294,399,504,651,676,721,796,901,926,1001,1126,1301,1406,1581,1826,1875,1980,2127,2232,2407,2652,2701,2848,3093}

static const int HT_L1[NT] = LIST_L1;
static const int HT_L2[NT] = LIST_L2;
static const int HT_LL[NT] = LIST_LL;
static const int HT_CG[NT] = LIST_CG;

__device__ constexpr int T_L1[NT] = LIST_L1;
__device__ constexpr int T_L2[NT] = LIST_L2;
__device__ constexpr int T_LL[NT] = LIST_LL;
__device__ constexpr int T_CG[NT] = LIST_CG;

__host__ __device__ constexpr int KLf(int l)   { return 256 - 64 * l; }
__host__ __device__ constexpr int FOFFf(int l) { return l == 0 ? 0 : l == 1 ? 256 : l == 2 ? 832 : 1472; }

static const int H_RBOFF[4] = {0, 8, 14, 18};
static const int H_NMAX[4]  = {8, 6, 4, 2};

typedef unsigned long long ull;

// packed fp32x2 math (sm_10x; FFMA2 only reachable via PTX)
__device__ __forceinline__ ull f2_fma(ull a, ull b, ull c) {
    ull d; asm("fma.rn.f32x2 %0, %1, %2, %3;" : "=l"(d) : "l"(a), "l"(b), "l"(c)); return d;
}
__device__ __forceinline__ ull f2_mul(ull a, ull b) {
    ull d; asm("mul.rn.f32x2 %0, %1, %2;" : "=l"(d) : "l"(a), "l"(b)); return d;
}
__device__ __forceinline__ ull f2_dup(float x) {
    ull d; unsigned xi = __float_as_uint(x);
    asm("mov.b64 %0, {%1, %1};" : "=l"(d) : "r"(xi)); return d;
}

// ---------------------------------------------------------------------------
// Host-built tables (one H2D memcpy node per call)
// Merged edge-weight matrix W: 256 outputs j = (l2*l2+b)*16 + (L*L+M);
// per-output entry list: ushort = cg_off | (edge_idx << 12), grouped by j.
// ---------------------------------------------------------------------------
struct Blob {
    float cg[NCG];
    unsigned short ent[NCG];   // packed (edge_idx<<12 | cg_off), grouped by output j
    int jse[256];              // (start<<16) | count
    int inv_off[60], inv_sh[60], inv_rb[60];
};

__device__ Blob  g_blob;
__device__ float g_bufA[(size_t)NATOM_MAX * FSTRIDE];
__device__ float g_bufB[(size_t)NATOM_MAX * FSTRIDE];
__device__ float g_wall[(size_t)NPAIR_MAX * 256];
__device__ float g_cemb[NATOM_MAX * 32];
__device__ int   g_counts[NATOM_MAX];
__device__ int   g_cursor[NATOM_MAX];
__device__ int   g_offsets[NATOM_MAX + 1];
__device__ int   g_sorted[NPAIR_MAX];

// ---------------------------------------------------------------------------
__global__ void cemb_kernel(const float* __restrict__ tab, const int* __restrict__ sp, int natoms) {
    int i = blockIdx.x * blockDim.x + threadIdx.x;
    if (i < natoms * 32) g_cemb[i] = tab[sp[i >> 5] * 32 + (i & 31)];
}

// ---------------------------------------------------------------------------
// counting sort of pairs by center
// ---------------------------------------------------------------------------
__global__ void zero_kernel(int natoms) {
    int i = blockIdx.x * blockDim.x + threadIdx.x;
    if (i < natoms) { g_counts[i] = 0; g_cursor[i] = 0; }
}
__global__ void hist_kernel(const int* __restrict__ centers, int np) {
    int p = blockIdx.x * blockDim.x + threadIdx.x;
    if (p < np) atomicAdd(&g_counts[centers[p]], 1);
}
__global__ void scan_kernel(int natoms) {
    __shared__ int ssum[1024];
    int t = threadIdx.x;
    int loc[5]; int s = 0;
#pragma unroll
    for (int i = 0; i < 5; i++) {
        int idx = t * 5 + i;
        loc[i] = s;
        int v = (idx < natoms) ? g_counts[idx] : 0;
        s += v;
    }
    ssum[t] = s;
    __syncthreads();
    for (int off = 1; off < 1024; off <<= 1) {
        int v = (t >= off) ? ssum[t - off] : 0;
        __syncthreads();
        ssum[t] += v;
        __syncthreads();
    }
    int pre = (t > 0) ? ssum[t - 1] : 0;
#pragma unroll
    for (int i = 0; i < 5; i++) {
        int idx = t * 5 + i;
        if (idx <= natoms) g_offsets[idx] = pre + loc[i];
    }
}
__global__ void rank_kernel(const int* __restrict__ centers, int np) {
    int p = blockIdx.x * blockDim.x + threadIdx.x;
    if (p < np) {
        int c = centers[p];
        int r = atomicAdd(&g_cursor[c], 1);
        g_sorted[g_offsets[c] + r] = p;
    }
}

// ---------------------------------------------------------------------------
// merged edge-weight build: g_wall[p][j], j = (l2^2+b)*16 + L^2+M, 256 outputs.
// W[j] = sum over contributing (l1,a): edge[l1^2+a] * cg[cg_off]
// warp per pair, lane covers j = lane + 32*ii.
// ---------------------------------------------------------------------------
#define PPB 16
__global__ void __launch_bounds__(128) wcomp_kernel(
    const float* __restrict__ sh, const float* __restrict__ rb, int np) {
    __shared__ float s_cg[NCG];
    __shared__ unsigned short s_ent[NCG];
    __shared__ int s_jse[256];
    __shared__ float s_edge[4][16];
    int tid = threadIdx.x;
    for (int i = tid; i < NCG; i += 128) { s_cg[i] = g_blob.cg[i]; s_ent[i] = g_blob.ent[i]; }
    for (int i = tid; i < 256; i += 128) s_jse[i] = g_blob.jse[i];
    __syncthreads();
    int warp = tid >> 5, lane = tid & 31;
#pragma unroll
    for (int pi = 0; pi < PPB / 4; pi++) {
        int p = blockIdx.x * PPB + warp + pi * 4;
        if (p >= np) break;
        if (lane < 16) {
            int l = (lane >= 9) ? 3 : (lane >= 4) ? 2 : (lane >= 1) ? 1 : 0;
            int rboff = (l == 3) ? 18 : (l == 2) ? 14 : (l == 1) ? 8 : 0;
            int rbsz = 8 - 2 * l;
            float rs = 0.f;
            for (int n = 0; n < rbsz; n++) rs += rb[(size_t)p * 20 + rboff + n];
            s_edge[warp][lane] = 0.1f * sh[(size_t)p * 16 + lane] * rs;
        }
        __syncwarp();
        float* wp = g_wall + (size_t)p * 256;
#pragma unroll
        for (int ii = 0; ii < 8; ii++) {
            int j = lane + 32 * ii;
            int se = s_jse[j];
            int st = se >> 16, cnt = se & 0xffff;
            float s = 0.f;
            for (int e = 0; e < cnt; e++) {
                unsigned en = s_ent[st + e];
                s += s_edge[warp][en >> 12] * s_cg[en & 0xfff];
            }
            wp[j] = s;
        }
        __syncwarp();
    }
}

// ---------------------------------------------------------------------------
// invariant MP, gather form w/ double-buffered staging.
// ---------------------------------------------------------------------------
__global__ void __launch_bounds__(128) inv_kernel(
    const float* __restrict__ sh, const float* __restrict__ rb,
    const int* __restrict__ neighbors, float* __restrict__ bufA, int natoms) {
    __shared__ float s_in[2][68];   // [0:16) sh, [16:36) rb, [36:68) emb
    int c = blockIdx.x;
    int tid = threadIdx.x, warp = tid >> 5, lane = tid & 31;
    int offj[15], shi[15], rbi[15];
#pragma unroll
    for (int ii = 0; ii < 15; ii++) {
        int j = warp + 4 * ii;
        offj[ii] = g_blob.inv_off[j];
        shi[ii]  = g_blob.inv_sh[j];
        rbi[ii]  = g_blob.inv_rb[j];
    }
    float acc[15];
#pragma unroll
    for (int ii = 0; ii < 15; ii++) acc[ii] = 0.f;

    int beg = g_offsets[c], end = g_offsets[c + 1];
    if (beg < end) {
        int p0 = g_sorted[beg];
        if (tid < 16)      s_in[0][tid] = sh[(size_t)p0 * 16 + tid];
        else if (tid < 36) s_in[0][tid] = rb[(size_t)p0 * 20 + (tid - 16)];
        else if (tid < 68) s_in[0][tid] = g_cemb[neighbors[p0] * 32 + (tid - 36)];
    }
    __syncthreads();
    for (int i = beg; i < end; i++) {
        int cur = (i - beg) & 1;
        float nst = 0.f;
        bool more = (i + 1 < end);
        if (more && tid < 68) {
            int pn = g_sorted[i + 1];
            if (tid < 16)      nst = sh[(size_t)pn * 16 + tid];
            else if (tid < 36) nst = rb[(size_t)pn * 20 + (tid - 16)];
            else               nst = g_cemb[neighbors[pn] * 32 + (tid - 36)];
        }
        float e = s_in[cur][36 + lane];
#pragma unroll
        for (int ii = 0; ii < 15; ii++)
            acc[ii] += s_in[cur][shi[ii]] * s_in[cur][16 + rbi[ii]] * e;
        if (more && tid < 68) s_in[cur ^ 1][tid] = nst;
        __syncthreads();
    }
    float* fb = bufA + (size_t)c * FSTRIDE;
#pragma unroll
    for (int ii = 0; ii < 15; ii++) fb[offj[ii] + lane] = 0.01f * acc[ii];
}

// ---------------------------------------------------------------------------
// fused in-place CG tensor product: feat += 0.1*TP(feat,feat).
// block = 512 threads = 16 warps = 4 atoms x 4 bands; band rotated by atom.
// ---------------------------------------------------------------------------
template <int LV>
__device__ __forceinline__ void tp_body(float* __restrict__ fb, int k, const float* s_cg2) {
    constexpr int MM = (LV + 1) * (LV + 1);
    ull A[MM], acc[MM];
#pragma unroll
    for (int l = 0; l <= LV; l++)
#pragma unroll
        for (int m = 0; m < 2 * l + 1; m++)
            A[l * l + m] = *reinterpret_cast<const ull*>(&fb[FOFFf(l) + m * KLf(l) + k]);
#pragma unroll
    for (int i = 0; i < MM; i++) acc[i] = 0ull;
#pragma unroll
    for (int tt = 0; tt < NT; tt++) {
        if (T_L1[tt] > LV || T_L2[tt] > LV || T_LL[tt] > LV) continue;
        const int l1 = T_L1[tt], l2 = T_L2[tt], L = T_LL[tt];
#pragma unroll
        for (int a = 0; a < 2 * l1 + 1; a++)
#pragma unroll
            for (int b = 0; b < 2 * l2 + 1; b++) {
                ull p = f2_mul(A[l1 * l1 + a], A[l2 * l2 + b]);
#pragma unroll
                for (int M = 0; M < 2 * L + 1; M++) {
                    ull c2 = *reinterpret_cast<const ull*>(
                        &s_cg2[2 * (T_CG[tt] + (a * (2 * l2 + 1) + b) * (2 * L + 1) + M)]);
                    acc[L * L + M] = f2_fma(c2, p, acc[L * L + M]);
                }
            }
    }
    ull sc = f2_dup(0.1f);
#pragma unroll
    for (int l = 0; l <= LV; l++)
#pragma unroll
        for (int m = 0; m < 2 * l + 1; m++) {
            int i = l * l + m;
            *reinterpret_cast<ull*>(&fb[FOFFf(l) + m * KLf(l) + k]) = f2_fma(sc, acc[i], A[i]);
        }
}

__global__ void __launch_bounds__(512) tp_fused_kernel(float* __restrict__ buf, int natoms) {
    __shared__ __align__(16) float s_cg2[2 * NCG];
    for (int i = threadIdx.x; i < NCG; i += 512) {
        float v = g_blob.cg[i];
        *reinterpret_cast<float2*>(&s_cg2[2 * i]) = make_float2(v, v);
    }
    __syncthreads();
    int warp = threadIdx.x >> 5, lane = threadIdx.x & 31;
    int atomI = blockIdx.x * 4 + (warp >> 2);
    if (atomI >= natoms) return;
    int bk = ((warp & 3) + atomI) & 3;   // band; LV = 3 - bk
    int k = bk * 64 + lane * 2;
    float* fb = buf + (size_t)atomI * FSTRIDE;
    if (bk == 0)      tp_body<3>(fb, k, s_cg2);
    else if (bk == 1) tp_body<2>(fb, k, s_cg2);
    else if (bk == 2) tp_body<1>(fb, k, s_cg2);
    else              tp_body<0>(fb, k, s_cg2);
}

// ---------------------------------------------------------------------------
// equivariant MP, gather form, merged dense W (16x16 per pair):
// out[c][L,M,k] = 0.1 * sum_pairs sum_{l2,b} W[(l2,b),(L,M)] * feats[nbr,l2,b,k]*cemb[nbr,k%32]
// block per center; band per warp rotated across SMSPs; double-buffered W smem.
// ---------------------------------------------------------------------------
template <int LV>
__device__ __forceinline__ void eq_acc2(const float* __restrict__ fan, ull ce2,
                                        const float* __restrict__ sw2, int k, ull* acc) {
    ull f[(LV + 1) * (LV + 1)];
#pragma unroll
    for (int l = 0; l <= LV; l++)
#pragma unroll
        for (int b = 0; b < 2 * l + 1; b++) {
            ull v = *reinterpret_cast<const ull*>(&fan[FOFFf(l) + b * KLf(l) + k]);
            f[l * l + b] = f2_mul(v, ce2);   // fold embed_centers
        }
#pragma unroll
    for (int l2 = 0; l2 <= LV; l2++)
#pragma unroll
        for (int b = 0; b < 2 * l2 + 1; b++) {
            ull fb = f[l2 * l2 + b];
            const int lm2 = l2 * l2 + b;
#pragma unroll
            for (int L = 0; L <= LV; L++)
#pragma unroll
                for (int M = 0; M < 2 * L + 1; M++) {
                    ull w2 = *reinterpret_cast<const ull*>(&sw2[2 * (lm2 * 16 + L * L + M)]);
                    acc[L * L + M] = f2_fma(w2, fb, acc[L * L + M]);
                }
        }
}

template <int LV>
__device__ __forceinline__ void eq_write2(float* __restrict__ mpb, int k, const ull* acc) {
    ull sc = f2_dup(0.1f);
#pragma unroll
    for (int L = 0; L <= LV; L++)
#pragma unroll
        for (int M = 0; M < 2 * L + 1; M++) {
            ull v = f2_mul(sc, acc[L * L + M]);
            *reinterpret_cast<ull*>(&mpb[FOFFf(L) + M * KLf(L) + k]) = v;
        }
}

__global__ void __launch_bounds__(128) eq_kernel(
    const int* __restrict__ neighbors,
    const float* __restrict__ bufA, float* __restrict__ bufB, int natoms) {
    __shared__ __align__(16) float s_w2[2][512];
    int c = blockIdx.x;
    int tid = threadIdx.x, warp = tid >> 5, lane = tid & 31;
    int bk = (warp + c) & 3;          // band; LV = 3 - bk
    int k = bk * 64 + lane * 2;
    ull acc[16];
#pragma unroll
    for (int i = 0; i < 16; i++) acc[i] = 0ull;

    int beg = g_offsets[c], end = g_offsets[c + 1];
    int nbr_cur = 0;
    if (beg < end) {
        int p0 = g_sorted[beg];
        nbr_cur = neighbors[p0];
        const float* wp = g_wall + (size_t)p0 * 256;
#pragma unroll
        for (int jj = 0; jj < 2; jj++) {
            int j = tid + jj * 128;
            float v = wp[j];
            *reinterpret_cast<float2*>(&s_w2[0][2 * j]) = make_float2(v, v);
        }
    }
    __syncthreads();
    for (int i = beg; i < end; i++) {
        int cur = (i - beg) & 1;
        bool more = (i + 1 < end);
        float nst0 = 0.f, nst1 = 0.f;
        int nbr_next = 0;
        if (more) {
            int pn = g_sorted[i + 1];
            nbr_next = neighbors[pn];
            const float* wp = g_wall + (size_t)pn * 256;
            nst0 = wp[tid];
            nst1 = wp[tid + 128];
        }
        const float* fan = bufA + (size_t)nbr_cur * FSTRIDE;
        float2 cef = *reinterpret_cast<const float2*>(&g_cemb[nbr_cur * 32 + 2 * (lane & 15)]);
        ull ce2 = *reinterpret_cast<ull*>(&cef);
        const float* sw = s_w2[cur];
        if (bk == 0)      eq_acc2<3>(fan, ce2, sw, k, acc);
        else if (bk == 1) eq_acc2<2>(fan, ce2, sw, k, acc);
        else if (bk == 2) eq_acc2<1>(fan, ce2, sw, k, acc);
        else              eq_acc2<0>(fan, ce2, sw, k, acc);
        if (more) {
            *reinterpret_cast<float2*>(&s_w2[cur ^ 1][2 * tid]) = make_float2(nst0, nst0);
            *reinterpret_cast<float2*>(&s_w2[cur ^ 1][2 * (tid + 128)]) = make_float2(nst1, nst1);
            nbr_cur = nbr_next;
        }
        __syncthreads();
    }
    float* mpb = bufB + (size_t)c * FSTRIDE;
    if (bk == 0)      eq_write2<3>(mpb, k, acc);
    else if (bk == 1) eq_write2<2>(mpb, k, acc);
    else if (bk == 2) eq_write2<1>(mpb, k, acc);
    else              eq_write2<0>(mpb, k, acc);
}

// ---------------------------------------------------------------------------
// energy: out[n] = sum_k buf[n,0,k] * cemb[n,k%32] * w[k] + b   (embed folded)
// ---------------------------------------------------------------------------
__global__ void energy_kernel(const float* __restrict__ buf,
                              const float* __restrict__ we, const float* __restrict__ be,
                              float* __restrict__ out, int natoms) {
    int atomI = blockIdx.x * 4 + (threadIdx.x >> 5);
    int lane = threadIdx.x & 31;
    if (atomI >= natoms) return;
    float e = g_cemb[atomI * 32 + lane];
    const float* fb = buf + (size_t)atomI * FSTRIDE;
    float s = 0.f;
#pragma unroll
    for (int kk = 0; kk < 8; kk++) s += fb[kk * 32 + lane] * we[kk * 32 + lane];
    s *= e;
#pragma unroll
    for (int o = 16; o > 0; o >>= 1) s += __shfl_xor_sync(0xffffffffu, s, o);
    if (lane == 0) out[atomI] = s + be[0];
}

// ---------------------------------------------------------------------------
// host: bit-exact numpy legacy RandomState(0).randn + table construction
// ---------------------------------------------------------------------------
static uint32_t s_mt[624];
static int s_mti;
static uint32_t mt_next() {
    if (s_mti >= 624) {
        for (int kk = 0; kk < 624; kk++) {
            uint32_t y = (s_mt[kk] & 0x80000000u) | (s_mt[(kk + 1) % 624] & 0x7fffffffu);
            s_mt[kk] = s_mt[(kk + 397) % 624] ^ (y >> 1) ^ ((y & 1u) ? 2567483615u : 0u);
        }
        s_mti = 0;
    }
    uint32_t y = s_mt[s_mti++];
    y ^= y >> 11;
    y ^= (y << 7) & 2636928640u;
    y ^= (y << 15) & 4022730752u;
    y ^= y >> 18;
    return y;
}
static double mt_double() {
    uint32_t a = mt_next() >> 5, b = mt_next() >> 6;
    return (a * 67108864.0 + b) / 9007199254740992.0;
}

static void build_blob(Blob& B) {
    uint32_t seed = 0;
    for (int pos = 0; pos < 624; pos++) {
        s_mt[pos] = seed;
        seed = 1812433253u * (seed ^ (seed >> 30)) + (uint32_t)pos + 1u;
    }
    s_mti = 624;
    int has_g = 0;
    double gcache = 0.0;
    for (int t = 0; t < NCG; t++) {
        double g;
        if (has_g) { g = gcache; has_g = 0; }
        else {
            double x1, x2, r2, f;
            do {
                x1 = 2.0 * mt_double() - 1.0;
                x2 = 2.0 * mt_double() - 1.0;
                r2 = x1 * x1 + x2 * x2;
            } while (r2 >= 1.0 || r2 == 0.0);
            f = sqrt(-2.0 * log(r2) / r2);
            gcache = f * x1;
            has_g = 1;
            g = f * x2;
        }
        B.cg[t] = (float)(g * 0.2);
    }
    // merged-W entry table: per output j=(l2^2+b)*16 + L^2+M, list of
    // (edge_idx = l1^2+a, cg_off) over all contributing triples.
    static unsigned short tmp[256][16];
    static int cnt[256];
    memset(cnt, 0, sizeof(cnt));
    for (int tt = 0; tt < NT; tt++) {
        int l1 = HT_L1[tt], l2 = HT_L2[tt], L = HT_LL[tt];
        for (int a = 0; a < 2 * l1 + 1; a++)
            for (int b = 0; b < 2 * l2 + 1; b++)
                for (int M = 0; M < 2 * L + 1; M++) {
                    int j = (l2 * l2 + b) * 16 + L * L + M;
                    int cg_off = HT_CG[tt] + (a * (2 * l2 + 1) + b) * (2 * L + 1) + M;
                    tmp[j][cnt[j]++] = (unsigned short)(((l1 * l1 + a) << 12) | cg_off);
                }
    }
    int pos = 0;
    for (int j = 0; j < 256; j++) {
        B.jse[j] = (pos << 16) | cnt[j];
        for (int e = 0; e < cnt[j]; e++) B.ent[pos++] = tmp[j][e];
    }
    // invariant combo table
    int j2 = 0;
    for (int l = 0; l < 4; l++)
        for (int m = 0; m < 2 * l + 1; m++)
            for (int n = 0; n < H_NMAX[l]; n++) {
                B.inv_off[j2] = FOFFf(l) + m * KLf(l) + n * 32;
                B.inv_sh[j2]  = l * l + m;
                B.inv_rb[j2]  = H_RBOFF[l] + n;
                j2++;
            }
}

static Blob h_blob;   // static: must outlive graph replays (memcpy node source)

// ---------------------------------------------------------------------------
extern "C" void kernel_launch(void* const* d_in, const int* in_sizes, int n_in,
                              void* d_out, int out_size) {
    const float* sh        = (const float*)d_in[0];
    const float* rb        = (const float*)d_in[1];
    const float* emb_table = (const float*)d_in[2];
    const float* w_energy  = (const float*)d_in[3];
    const float* b_energy  = (const float*)d_in[4];
    const int*   species   = (const int*)d_in[5];
    const int*   centers   = (const int*)d_in[6];
    const int*   neighbors = (const int*)d_in[7];
    int natoms = in_sizes[5];
    int np     = in_sizes[6];
    if (natoms > NATOM_MAX) natoms = NATOM_MAX;
    if (np > NPAIR_MAX)     np = NPAIR_MAX;
    float* out = (float*)d_out;

    build_blob(h_blob);
    cudaMemcpyToSymbolAsync(g_blob, &h_blob, sizeof(Blob), 0, cudaMemcpyHostToDevice, 0);

    float *bufA = nullptr, *bufB = nullptr;
    cudaGetSymbolAddress((void**)&bufA, g_bufA);
    cudaGetSymbolAddress((void**)&bufB, g_bufB);

    // embeddings + counting sort of pairs by center
    cemb_kernel<<<(natoms * 32 + 255) / 256, 256>>>(emb_table, species, natoms);
    zero_kernel<<<(natoms + 255) / 256, 256>>>(natoms);
    hist_kernel<<<(np + 255) / 256, 256>>>(centers, np);
    scan_kernel<<<1, 1024>>>(natoms);
    rank_kernel<<<(np + 255) / 256, 256>>>(centers, np);

    // merged per-pair edge-weight matrices (dense 16x16)
    wcomp_kernel<<<(np + PPB - 1) / PPB, 128>>>(sh, rb, np);

    // invariant MP (gather) -> bufA
    inv_kernel<<<natoms, 128>>>(sh, rb, neighbors, bufA, natoms);

    // cg_iterate #1 (fused bands)
    tp_fused_kernel<<<(natoms + 3) / 4, 512>>>(bufA, natoms);

    // equivariant MP: reads bufA (embed folded) + g_wall, writes bufB
    eq_kernel<<<natoms, 128>>>(neighbors, bufA, bufB, natoms);

    // cg_iterate #2
    tp_fused_kernel<<<(natoms + 3) / 4, 512>>>(bufB, natoms);

    // final embed folded into energy readout
    energy_kernel<<<(natoms + 3) / 4, 128>>>(bufB, w_energy, b_energy, out, natoms);
}